// round 2
// baseline (speedup 1.0000x reference)
#include <cuda_runtime.h>

#define BB 4
#define NN 8192
#define DD 32
#define KNB 16
#define M0 32
#define M1 32
#define M2 64
#define LEAKY 0.1f
#define TILE 2048
#define NCHUNK 2
#define CHUNK (NN / NCHUNK)

__device__ float4 g_xyzw[BB * NN];
__device__ float  g_feat[BB * NN * M0];
__device__ int    g_idx[BB * NN * KNB];
__device__ float  g_pd[NCHUNK * BB * NN * KNB];
__device__ int    g_pi[NCHUNK * BB * NN * KNB];

__device__ __forceinline__ float lrelu(float x) { return x > 0.f ? x : LEAKY * x; }

// packed f32x2 helpers (FFMA2 only reachable via PTX)
__device__ __forceinline__ unsigned long long pk2(float lo, float hi) {
    unsigned long long r;
    asm("mov.b64 %0, {%1, %2};" : "=l"(r) : "f"(lo), "f"(hi));
    return r;
}
__device__ __forceinline__ void upk2(unsigned long long v, float& lo, float& hi) {
    asm("mov.b64 {%0, %1}, %2;" : "=f"(lo), "=f"(hi) : "l"(v));
}
__device__ __forceinline__ unsigned long long fma2(unsigned long long a,
                                                   unsigned long long b,
                                                   unsigned long long c) {
    unsigned long long d;
    asm("fma.rn.f32x2 %0, %1, %2, %3;" : "=l"(d) : "l"(a), "l"(b), "l"(c));
    return d;
}

__device__ __forceinline__ void insert16(float (&bd)[KNB], int (&bi)[KNB],
                                         float d, int j) {
    bd[KNB - 1] = d;
    bi[KNB - 1] = j;
#pragma unroll
    for (int m = KNB - 1; m > 0; m--) {
        if (bd[m - 1] > bd[m]) {
            float td = bd[m - 1]; bd[m - 1] = bd[m]; bd[m] = td;
            int   ti = bi[m - 1]; bi[m - 1] = bi[m]; bi[m] = ti;
        } else break;
    }
}

// ---------------------------------------------------------------------------
// Kernel 1: pack xyz as float4(x,y,z,|p|^2); feat = W0[:,3:] @ points
// ---------------------------------------------------------------------------
__global__ void prep_kernel(const float* __restrict__ xyz,
                            const float* __restrict__ points,
                            const float* __restrict__ W0) {
    __shared__ __align__(16) float wfT[DD][M0];
    int tid = threadIdx.x;
    for (int i = tid; i < DD * M0; i += 128) {
        int c = i / M0, o = i % M0;
        wfT[c][o] = W0[o * 35 + 3 + c];
    }
    __syncthreads();

    int gq = blockIdx.x * 128 + tid;
    int b = gq / NN, n = gq % NN;

    const float* xb = xyz + (size_t)b * 3 * NN;
    float x = xb[n], y = xb[NN + n], z = xb[2 * NN + n];
    float sq = fmaf(x, x, fmaf(y, y, z * z));
    g_xyzw[gq] = make_float4(x, y, z, sq);

    float acc[M0];
#pragma unroll
    for (int o = 0; o < M0; o++) acc[o] = 0.f;

    const float* pb = points + (size_t)b * DD * NN + n;
#pragma unroll 4
    for (int c = 0; c < DD; c++) {
        float p = pb[(size_t)c * NN];
        const float4* w4 = (const float4*)wfT[c];
#pragma unroll
        for (int o4 = 0; o4 < M0 / 4; o4++) {
            float4 w = w4[o4];
            acc[o4 * 4 + 0] = fmaf(w.x, p, acc[o4 * 4 + 0]);
            acc[o4 * 4 + 1] = fmaf(w.y, p, acc[o4 * 4 + 1]);
            acc[o4 * 4 + 2] = fmaf(w.z, p, acc[o4 * 4 + 2]);
            acc[o4 * 4 + 3] = fmaf(w.w, p, acc[o4 * 4 + 3]);
        }
    }
    float4* fo = (float4*)(g_feat + (size_t)gq * M0);
#pragma unroll
    for (int o4 = 0; o4 < M0 / 4; o4++)
        fo[o4] = make_float4(acc[o4 * 4 + 0], acc[o4 * 4 + 1],
                             acc[o4 * 4 + 2], acc[o4 * 4 + 3]);
}

// ---------------------------------------------------------------------------
// Kernel 2: partial kNN over a candidate chunk. grid (N/256, B, NCHUNK).
// Distance omits +q.w (monotone per query). Groups of 8 candidates share one
// fmin-tree threshold test so the common path has a single branch per 8.
// ---------------------------------------------------------------------------
__global__ void __launch_bounds__(256) knn_kernel(void) {
    __shared__ __align__(16) float4 tile[TILE];
    int b = blockIdx.y;
    int chunk = blockIdx.z;
    int q = blockIdx.x * 256 + threadIdx.x;

    float4 qf = g_xyzw[b * NN + q];
    float nqx = -2.f * qf.x, nqy = -2.f * qf.y, nqz = -2.f * qf.z;

    float bd[KNB];
    int   bi[KNB];
#pragma unroll
    for (int m = 0; m < KNB; m++) { bd[m] = 3.4e38f; bi[m] = -1; }

    int base = chunk * CHUNK;
    for (int t = 0; t < CHUNK / TILE; t++) {
        __syncthreads();
        const float4* src = &g_xyzw[b * NN + base + t * TILE];
        for (int i = threadIdx.x; i < TILE; i += 256) tile[i] = src[i];
        __syncthreads();

#pragma unroll 1
        for (int j0 = 0; j0 < TILE; j0 += 8) {
            float dv[8];
#pragma unroll
            for (int u = 0; u < 8; u++) {
                float4 c = tile[j0 + u];
                dv[u] = fmaf(nqx, c.x, fmaf(nqy, c.y, fmaf(nqz, c.z, c.w)));
            }
            float m01 = fminf(dv[0], dv[1]);
            float m23 = fminf(dv[2], dv[3]);
            float m45 = fminf(dv[4], dv[5]);
            float m67 = fminf(dv[6], dv[7]);
            float mall = fminf(fminf(m01, m23), fminf(m45, m67));
            if (mall < bd[KNB - 1]) {
#pragma unroll
                for (int u = 0; u < 8; u++) {
                    if (dv[u] < bd[KNB - 1])
                        insert16(bd, bi, dv[u], base + t * TILE + j0 + u);
                }
            }
        }
    }

    size_t part = ((size_t)chunk * BB * NN + (size_t)b * NN + q) * KNB;
    float4* dp = (float4*)(g_pd + part);
    int4*   ip = (int4*)(g_pi + part);
#pragma unroll
    for (int m4 = 0; m4 < KNB / 4; m4++) {
        dp[m4] = make_float4(bd[m4 * 4 + 0], bd[m4 * 4 + 1],
                             bd[m4 * 4 + 2], bd[m4 * 4 + 3]);
        ip[m4] = make_int4(bi[m4 * 4 + 0], bi[m4 * 4 + 1],
                           bi[m4 * 4 + 2], bi[m4 * 4 + 3]);
    }
}

// ---------------------------------------------------------------------------
// Kernel 2b: merge NCHUNK sorted partial lists -> g_idx. 1 thread / query.
// Chunk 0 seeds; later chunks (higher j) inserted with strict < so boundary
// ties keep the lower index (matches jax top_k tie order).
// ---------------------------------------------------------------------------
__global__ void merge_kernel(void) {
    int gq = blockIdx.x * 128 + threadIdx.x;

    float bd[KNB];
    int   bi[KNB];
    const float4* dp0 = (const float4*)(g_pd + (size_t)gq * KNB);
    const int4*   ip0 = (const int4*)(g_pi + (size_t)gq * KNB);
#pragma unroll
    for (int m4 = 0; m4 < KNB / 4; m4++) {
        float4 d = dp0[m4]; int4 i = ip0[m4];
        bd[m4 * 4 + 0] = d.x; bd[m4 * 4 + 1] = d.y;
        bd[m4 * 4 + 2] = d.z; bd[m4 * 4 + 3] = d.w;
        bi[m4 * 4 + 0] = i.x; bi[m4 * 4 + 1] = i.y;
        bi[m4 * 4 + 2] = i.z; bi[m4 * 4 + 3] = i.w;
    }

#pragma unroll
    for (int c = 1; c < NCHUNK; c++) {
        size_t off = ((size_t)c * BB * NN + gq) * KNB;
        const float* pd = g_pd + off;
        const int*   pi = g_pi + off;
#pragma unroll
        for (int m = 0; m < KNB; m++) {
            float d = pd[m];
            if (d < bd[KNB - 1]) insert16(bd, bi, d, pi[m]);
            else break;   // sorted ascending: no later entry qualifies
        }
    }

    int4* op = (int4*)(g_idx + (size_t)gq * KNB);
#pragma unroll
    for (int m4 = 0; m4 < KNB / 4; m4++)
        op[m4] = make_int4(bi[m4 * 4 + 0], bi[m4 * 4 + 1],
                           bi[m4 * 4 + 2], bi[m4 * 4 + 3]);
}

// ---------------------------------------------------------------------------
// Kernel 3: gather + 3-layer MLP (layers 1/2 on packed fma.rn.f32x2) + max
// over K. block 128 = 8 queries x 16 neighbor-threads.
// ---------------------------------------------------------------------------
__global__ void __launch_bounds__(128) mlp_kernel(const float* __restrict__ W0,
                                                  const float* __restrict__ W1,
                                                  const float* __restrict__ W2,
                                                  float* __restrict__ out) {
    __shared__ __align__(16) float w0x[M0][4];
    __shared__ __align__(16) unsigned long long w1p[M0][M1 / 2];  // [c][opair]
    __shared__ __align__(16) unsigned long long w2p[M1][M2 / 2];  // [c][opair]
    __shared__ float stage[8][M2];

    int tid = threadIdx.x;
    for (int i = tid; i < M0 * 4; i += 128) {
        int o = i / 4, c = i % 4;
        w0x[o][c] = (c < 3) ? W0[o * 35 + c] : 0.f;
    }
    for (int i = tid; i < M0 * (M1 / 2); i += 128) {
        int c = i / (M1 / 2), p = i % (M1 / 2);
        w1p[c][p] = pk2(W1[(2 * p) * M0 + c], W1[(2 * p + 1) * M0 + c]);
    }
    for (int i = tid; i < M1 * (M2 / 2); i += 128) {
        int c = i / (M2 / 2), p = i % (M2 / 2);
        w2p[c][p] = pk2(W2[(2 * p) * M1 + c], W2[(2 * p + 1) * M1 + c]);
    }
    __syncthreads();

    int g = tid >> 4, k = tid & 15;
    int gq = blockIdx.x * 8 + g;
    int b = gq / NN;

    int j = g_idx[(size_t)gq * KNB + k];
    float4 qf = g_xyzw[gq];
    float4 cf = g_xyzw[b * NN + j];
    float rx = cf.x - qf.x, ry = cf.y - qf.y, rz = cf.z - qf.z;

    // layer 0: h0 = lrelu(W0[:, :3] @ rel + feat[j])
    float h0[M0];
    const float4* fg = (const float4*)(g_feat + ((size_t)b * NN + j) * M0);
#pragma unroll
    for (int o4 = 0; o4 < M0 / 4; o4++) {
        float4 f = fg[o4];
        float fv[4] = {f.x, f.y, f.z, f.w};
#pragma unroll
        for (int u = 0; u < 4; u++) {
            float4 w = *(const float4*)w0x[o4 * 4 + u];
            h0[o4 * 4 + u] = lrelu(fmaf(w.x, rx, fmaf(w.y, ry, fmaf(w.z, rz, fv[u]))));
        }
    }

    // layer 1 (f32x2): 16 output-pair accumulators
    unsigned long long acc1[M1 / 2];
#pragma unroll
    for (int p = 0; p < M1 / 2; p++) acc1[p] = 0ull;
#pragma unroll
    for (int c = 0; c < M0; c++) {
        unsigned long long hp = pk2(h0[c], h0[c]);
        const ulonglong2* wv = (const ulonglong2*)w1p[c];
#pragma unroll
        for (int p2 = 0; p2 < M1 / 4; p2++) {
            ulonglong2 w = wv[p2];
            acc1[2 * p2 + 0] = fma2(w.x, hp, acc1[2 * p2 + 0]);
            acc1[2 * p2 + 1] = fma2(w.y, hp, acc1[2 * p2 + 1]);
        }
    }
    // h1 stored pre-packed as {v,v} pairs for layer 2 broadcasts
    unsigned long long h1p[M1];
#pragma unroll
    for (int p = 0; p < M1 / 2; p++) {
        float a, bv;
        upk2(acc1[p], a, bv);
        a = lrelu(a); bv = lrelu(bv);
        h1p[2 * p + 0] = pk2(a, a);
        h1p[2 * p + 1] = pk2(bv, bv);
    }

    // layer 2 (f32x2) + lrelu + max over 16 neighbor lanes, 8 outputs/chunk
#pragma unroll 1
    for (int ch = 0; ch < M2 / 8; ch++) {
        unsigned long long a01 = 0ull, a23 = 0ull, a45 = 0ull, a67 = 0ull;
#pragma unroll
        for (int c = 0; c < M1; c++) {
            unsigned long long hp = h1p[c];
            const ulonglong2* wv = (const ulonglong2*)&w2p[c][ch * 4];
            ulonglong2 wa = wv[0], wb = wv[1];
            a01 = fma2(wa.x, hp, a01);
            a23 = fma2(wa.y, hp, a23);
            a45 = fma2(wb.x, hp, a45);
            a67 = fma2(wb.y, hp, a67);
        }
        float v[8];
        upk2(a01, v[0], v[1]);
        upk2(a23, v[2], v[3]);
        upk2(a45, v[4], v[5]);
        upk2(a67, v[6], v[7]);
#pragma unroll
        for (int u = 0; u < 8; u++) v[u] = lrelu(v[u]);
#pragma unroll
        for (int s = 8; s >= 1; s >>= 1) {
#pragma unroll
            for (int u = 0; u < 8; u++)
                v[u] = fmaxf(v[u], __shfl_xor_sync(0xffffffffu, v[u], s));
        }
        if (k == 0) {
#pragma unroll
            for (int u = 0; u < 8; u++) stage[g][ch * 8 + u] = v[u];
        }
    }
    __syncthreads();

    // coalesced store: out[b][o][n]
    int gq0 = blockIdx.x * 8;
    int b0 = gq0 / NN, n0 = gq0 % NN;
    for (int i = tid; i < 8 * M2; i += 128) {
        int o = i >> 3, gi = i & 7;
        out[((size_t)b0 * M2 + o) * NN + (n0 + gi)] = stage[gi][o];
    }
}

extern "C" void kernel_launch(void* const* d_in, const int* in_sizes, int n_in,
                              void* d_out, int out_size) {
    const float* xyz    = (const float*)d_in[0];
    const float* points = (const float*)d_in[1];
    const float* W0     = (const float*)d_in[2];
    const float* W1     = (const float*)d_in[3];
    const float* W2     = (const float*)d_in[4];
    float* out = (float*)d_out;

    prep_kernel<<<BB * NN / 128, 128>>>(xyz, points, W0);

    dim3 g2(NN / 256, BB, NCHUNK);
    knn_kernel<<<g2, 256>>>();

    merge_kernel<<<BB * NN / 128, 128>>>();

    mlp_kernel<<<BB * NN / 8, 128>>>(W0, W1, W2, out);
}

// round 3
// speedup vs baseline: 2.5993x; 2.5993x over previous
#include <cuda_runtime.h>

#define BB 4
#define NN 8192
#define DD 32
#define KNB 16
#define M0 32
#define M1 32
#define M2 64
#define LEAKY 0.1f
#define NCHUNK 4
#define CHUNK (NN / NCHUNK)   // 2048

__device__ float4 g_xyzw[BB * NN];
__device__ float  g_feat[BB * NN * M0];
__device__ int    g_idx[BB * NN * KNB];
__device__ float  g_pd[NCHUNK * BB * NN * KNB];
__device__ int    g_pi[NCHUNK * BB * NN * KNB];

__device__ __forceinline__ float lrelu(float x) { return x > 0.f ? x : LEAKY * x; }

// packed f32x2 helpers (FFMA2 only reachable via PTX)
__device__ __forceinline__ unsigned long long pk2(float lo, float hi) {
    unsigned long long r;
    asm("mov.b64 %0, {%1, %2};" : "=l"(r) : "f"(lo), "f"(hi));
    return r;
}
__device__ __forceinline__ void upk2(unsigned long long v, float& lo, float& hi) {
    asm("mov.b64 {%0, %1}, %2;" : "=f"(lo), "=f"(hi) : "l"(v));
}
__device__ __forceinline__ unsigned long long fma2(unsigned long long a,
                                                   unsigned long long b,
                                                   unsigned long long c) {
    unsigned long long d;
    asm("fma.rn.f32x2 %0, %1, %2, %3;" : "=l"(d) : "l"(a), "l"(b), "l"(c));
    return d;
}

__device__ __forceinline__ void insert16(float (&bd)[KNB], int (&bi)[KNB],
                                         float d, int j) {
    bd[KNB - 1] = d;
    bi[KNB - 1] = j;
#pragma unroll
    for (int m = KNB - 1; m > 0; m--) {
        if (bd[m - 1] > bd[m]) {
            float td = bd[m - 1]; bd[m - 1] = bd[m]; bd[m] = td;
            int   ti = bi[m - 1]; bi[m - 1] = bi[m]; bi[m] = ti;
        } else break;
    }
}

// ---------------------------------------------------------------------------
// Kernel 1: pack xyz as float4(x,y,z,|p|^2); feat = W0[:,3:] @ points
// ---------------------------------------------------------------------------
__global__ void prep_kernel(const float* __restrict__ xyz,
                            const float* __restrict__ points,
                            const float* __restrict__ W0) {
    __shared__ __align__(16) float wfT[DD][M0];
    int tid = threadIdx.x;
    for (int i = tid; i < DD * M0; i += 128) {
        int c = i / M0, o = i % M0;
        wfT[c][o] = W0[o * 35 + 3 + c];
    }
    __syncthreads();

    int gq = blockIdx.x * 128 + tid;
    int b = gq / NN, n = gq % NN;

    const float* xb = xyz + (size_t)b * 3 * NN;
    float x = xb[n], y = xb[NN + n], z = xb[2 * NN + n];
    float sq = fmaf(x, x, fmaf(y, y, z * z));
    g_xyzw[gq] = make_float4(x, y, z, sq);

    float acc[M0];
#pragma unroll
    for (int o = 0; o < M0; o++) acc[o] = 0.f;

    const float* pb = points + (size_t)b * DD * NN + n;
#pragma unroll 4
    for (int c = 0; c < DD; c++) {
        float p = pb[(size_t)c * NN];
        const float4* w4 = (const float4*)wfT[c];
#pragma unroll
        for (int o4 = 0; o4 < M0 / 4; o4++) {
            float4 w = w4[o4];
            acc[o4 * 4 + 0] = fmaf(w.x, p, acc[o4 * 4 + 0]);
            acc[o4 * 4 + 1] = fmaf(w.y, p, acc[o4 * 4 + 1]);
            acc[o4 * 4 + 2] = fmaf(w.z, p, acc[o4 * 4 + 2]);
            acc[o4 * 4 + 3] = fmaf(w.w, p, acc[o4 * 4 + 3]);
        }
    }
    float4* fo = (float4*)(g_feat + (size_t)gq * M0);
#pragma unroll
    for (int o4 = 0; o4 < M0 / 4; o4++)
        fo[o4] = make_float4(acc[o4 * 4 + 0], acc[o4 * 4 + 1],
                             acc[o4 * 4 + 2], acc[o4 * 4 + 3]);
}

// ---------------------------------------------------------------------------
// Kernel 2: partial kNN over one candidate chunk (R1-proven inner loop).
// grid (N/256, B, NCHUNK), block 256, 1 thread = 1 query.
// Distance formula identical to R1 (includes q.w) -> identical fp ranking.
// ---------------------------------------------------------------------------
__global__ void __launch_bounds__(256) knn_kernel(void) {
    __shared__ __align__(16) float4 tile[CHUNK];
    int b = blockIdx.y;
    int chunk = blockIdx.z;
    int q = blockIdx.x * 256 + threadIdx.x;

    float4 qf = g_xyzw[b * NN + q];
    float nqx = -2.f * qf.x, nqy = -2.f * qf.y, nqz = -2.f * qf.z;

    float bd[KNB];
    int   bi[KNB];
#pragma unroll
    for (int m = 0; m < KNB; m++) { bd[m] = 3.4e38f; bi[m] = -1; }

    int base = chunk * CHUNK;
    const float4* src = &g_xyzw[b * NN + base];
    for (int i = threadIdx.x; i < CHUNK; i += 256) tile[i] = src[i];
    __syncthreads();

#pragma unroll 4
    for (int j = 0; j < CHUNK; j++) {
        float4 c = tile[j];
        float d = fmaf(nqx, c.x, fmaf(nqy, c.y, fmaf(nqz, c.z, qf.w + c.w)));
        if (d < bd[KNB - 1]) insert16(bd, bi, d, base + j);
    }

    size_t part = ((size_t)chunk * BB * NN + (size_t)b * NN + q) * KNB;
    float4* dp = (float4*)(g_pd + part);
    int4*   ip = (int4*)(g_pi + part);
#pragma unroll
    for (int m4 = 0; m4 < KNB / 4; m4++) {
        dp[m4] = make_float4(bd[m4 * 4 + 0], bd[m4 * 4 + 1],
                             bd[m4 * 4 + 2], bd[m4 * 4 + 3]);
        ip[m4] = make_int4(bi[m4 * 4 + 0], bi[m4 * 4 + 1],
                           bi[m4 * 4 + 2], bi[m4 * 4 + 3]);
    }
}

// ---------------------------------------------------------------------------
// Kernel 2b: merge NCHUNK sorted partial lists -> g_idx. 1 thread / query.
// Chunks processed in ascending index order; strict < insert keeps the
// lower-index entry on ties (matches jax.lax.top_k tie order).
// ---------------------------------------------------------------------------
__global__ void merge_kernel(void) {
    int gq = blockIdx.x * 128 + threadIdx.x;

    float bd[KNB];
    int   bi[KNB];
    const float4* dp0 = (const float4*)(g_pd + (size_t)gq * KNB);
    const int4*   ip0 = (const int4*)(g_pi + (size_t)gq * KNB);
#pragma unroll
    for (int m4 = 0; m4 < KNB / 4; m4++) {
        float4 d = dp0[m4]; int4 i = ip0[m4];
        bd[m4 * 4 + 0] = d.x; bd[m4 * 4 + 1] = d.y;
        bd[m4 * 4 + 2] = d.z; bd[m4 * 4 + 3] = d.w;
        bi[m4 * 4 + 0] = i.x; bi[m4 * 4 + 1] = i.y;
        bi[m4 * 4 + 2] = i.z; bi[m4 * 4 + 3] = i.w;
    }

#pragma unroll 1
    for (int c = 1; c < NCHUNK; c++) {
        size_t off = ((size_t)c * BB * NN + gq) * KNB;
        const float* pd = g_pd + off;
        const int*   pi = g_pi + off;
#pragma unroll 1
        for (int m = 0; m < KNB; m++) {
            float d = pd[m];
            if (d < bd[KNB - 1]) insert16(bd, bi, d, pi[m]);
            else break;   // partial list sorted ascending
        }
    }

    int4* op = (int4*)(g_idx + (size_t)gq * KNB);
#pragma unroll
    for (int m4 = 0; m4 < KNB / 4; m4++)
        op[m4] = make_int4(bi[m4 * 4 + 0], bi[m4 * 4 + 1],
                           bi[m4 * 4 + 2], bi[m4 * 4 + 3]);
}

// ---------------------------------------------------------------------------
// Kernel 3: gather + 3-layer MLP (layers 1/2 on packed fma.rn.f32x2) + max
// over K. block 128 = 8 queries x 16 neighbor-threads. (unchanged from R2,
// measured 162us)
// ---------------------------------------------------------------------------
__global__ void __launch_bounds__(128) mlp_kernel(const float* __restrict__ W0,
                                                  const float* __restrict__ W1,
                                                  const float* __restrict__ W2,
                                                  float* __restrict__ out) {
    __shared__ __align__(16) float w0x[M0][4];
    __shared__ __align__(16) unsigned long long w1p[M0][M1 / 2];
    __shared__ __align__(16) unsigned long long w2p[M1][M2 / 2];
    __shared__ float stage[8][M2];

    int tid = threadIdx.x;
    for (int i = tid; i < M0 * 4; i += 128) {
        int o = i / 4, c = i % 4;
        w0x[o][c] = (c < 3) ? W0[o * 35 + c] : 0.f;
    }
    for (int i = tid; i < M0 * (M1 / 2); i += 128) {
        int c = i / (M1 / 2), p = i % (M1 / 2);
        w1p[c][p] = pk2(W1[(2 * p) * M0 + c], W1[(2 * p + 1) * M0 + c]);
    }
    for (int i = tid; i < M1 * (M2 / 2); i += 128) {
        int c = i / (M2 / 2), p = i % (M2 / 2);
        w2p[c][p] = pk2(W2[(2 * p) * M1 + c], W2[(2 * p + 1) * M1 + c]);
    }
    __syncthreads();

    int g = tid >> 4, k = tid & 15;
    int gq = blockIdx.x * 8 + g;
    int b = gq / NN;

    int j = g_idx[(size_t)gq * KNB + k];
    float4 qf = g_xyzw[gq];
    float4 cf = g_xyzw[b * NN + j];
    float rx = cf.x - qf.x, ry = cf.y - qf.y, rz = cf.z - qf.z;

    float h0[M0];
    const float4* fg = (const float4*)(g_feat + ((size_t)b * NN + j) * M0);
#pragma unroll
    for (int o4 = 0; o4 < M0 / 4; o4++) {
        float4 f = fg[o4];
        float fv[4] = {f.x, f.y, f.z, f.w};
#pragma unroll
        for (int u = 0; u < 4; u++) {
            float4 w = *(const float4*)w0x[o4 * 4 + u];
            h0[o4 * 4 + u] = lrelu(fmaf(w.x, rx, fmaf(w.y, ry, fmaf(w.z, rz, fv[u]))));
        }
    }

    unsigned long long acc1[M1 / 2];
#pragma unroll
    for (int p = 0; p < M1 / 2; p++) acc1[p] = 0ull;
#pragma unroll
    for (int c = 0; c < M0; c++) {
        unsigned long long hp = pk2(h0[c], h0[c]);
        const ulonglong2* wv = (const ulonglong2*)w1p[c];
#pragma unroll
        for (int p2 = 0; p2 < M1 / 4; p2++) {
            ulonglong2 w = wv[p2];
            acc1[2 * p2 + 0] = fma2(w.x, hp, acc1[2 * p2 + 0]);
            acc1[2 * p2 + 1] = fma2(w.y, hp, acc1[2 * p2 + 1]);
        }
    }
    unsigned long long h1p[M1];
#pragma unroll
    for (int p = 0; p < M1 / 2; p++) {
        float a, bv;
        upk2(acc1[p], a, bv);
        a = lrelu(a); bv = lrelu(bv);
        h1p[2 * p + 0] = pk2(a, a);
        h1p[2 * p + 1] = pk2(bv, bv);
    }

#pragma unroll 1
    for (int ch = 0; ch < M2 / 8; ch++) {
        unsigned long long a01 = 0ull, a23 = 0ull, a45 = 0ull, a67 = 0ull;
#pragma unroll
        for (int c = 0; c < M1; c++) {
            unsigned long long hp = h1p[c];
            const ulonglong2* wv = (const ulonglong2*)&w2p[c][ch * 4];
            ulonglong2 wa = wv[0], wb = wv[1];
            a01 = fma2(wa.x, hp, a01);
            a23 = fma2(wa.y, hp, a23);
            a45 = fma2(wb.x, hp, a45);
            a67 = fma2(wb.y, hp, a67);
        }
        float v[8];
        upk2(a01, v[0], v[1]);
        upk2(a23, v[2], v[3]);
        upk2(a45, v[4], v[5]);
        upk2(a67, v[6], v[7]);
#pragma unroll
        for (int u = 0; u < 8; u++) v[u] = lrelu(v[u]);
#pragma unroll
        for (int s = 8; s >= 1; s >>= 1) {
#pragma unroll
            for (int u = 0; u < 8; u++)
                v[u] = fmaxf(v[u], __shfl_xor_sync(0xffffffffu, v[u], s));
        }
        if (k == 0) {
#pragma unroll
            for (int u = 0; u < 8; u++) stage[g][ch * 8 + u] = v[u];
        }
    }
    __syncthreads();

    int gq0 = blockIdx.x * 8;
    int b0 = gq0 / NN, n0 = gq0 % NN;
    for (int i = tid; i < 8 * M2; i += 128) {
        int o = i >> 3, gi = i & 7;
        out[((size_t)b0 * M2 + o) * NN + (n0 + gi)] = stage[gi][o];
    }
}

extern "C" void kernel_launch(void* const* d_in, const int* in_sizes, int n_in,
                              void* d_out, int out_size) {
    const float* xyz    = (const float*)d_in[0];
    const float* points = (const float*)d_in[1];
    const float* W0     = (const float*)d_in[2];
    const float* W1     = (const float*)d_in[3];
    const float* W2     = (const float*)d_in[4];
    float* out = (float*)d_out;

    prep_kernel<<<BB * NN / 128, 128>>>(xyz, points, W0);

    dim3 g2(NN / 256, BB, NCHUNK);
    knn_kernel<<<g2, 256>>>();

    merge_kernel<<<BB * NN / 128, 128>>>();

    mlp_kernel<<<BB * NN / 8, 128>>>(W0, W1, W2, out);
}

// round 4
// speedup vs baseline: 7.9269x; 3.0497x over previous
#include <cuda_runtime.h>

#define BB 4
#define NN 8192
#define DD 32
#define KNB 16
#define M0 32
#define M1 32
#define M2 64
#define LEAKY 0.1f
#define KTILE 1024
#define RINGN 24

__device__ float4 g_xyzw[BB * NN];
__device__ float  g_feat[BB * NN * M0];
__device__ int    g_idx[BB * NN * KNB];

__device__ __forceinline__ float lrelu(float x) { return x > 0.f ? x : LEAKY * x; }

// packed f32x2 helpers (FFMA2 only reachable via PTX)
__device__ __forceinline__ unsigned long long pk2(float lo, float hi) {
    unsigned long long r;
    asm("mov.b64 %0, {%1, %2};" : "=l"(r) : "f"(lo), "f"(hi));
    return r;
}
__device__ __forceinline__ void upk2(unsigned long long v, float& lo, float& hi) {
    asm("mov.b64 {%0, %1}, %2;" : "=f"(lo), "=f"(hi) : "l"(v));
}
__device__ __forceinline__ unsigned long long fma2(unsigned long long a,
                                                   unsigned long long b,
                                                   unsigned long long c) {
    unsigned long long d;
    asm("fma.rn.f32x2 %0, %1, %2, %3;" : "=l"(d) : "l"(a), "l"(b), "l"(c));
    return d;
}

// ---------------------------------------------------------------------------
// Kernel 1: pack xyz as float4(x,y,z,|p|^2); feat = W0[:,3:] @ points
// ---------------------------------------------------------------------------
__global__ void prep_kernel(const float* __restrict__ xyz,
                            const float* __restrict__ points,
                            const float* __restrict__ W0) {
    __shared__ __align__(16) float wfT[DD][M0];
    int tid = threadIdx.x;
    for (int i = tid; i < DD * M0; i += 128) {
        int c = i / M0, o = i % M0;
        wfT[c][o] = W0[o * 35 + 3 + c];
    }
    __syncthreads();

    int gq = blockIdx.x * 128 + tid;
    int b = gq / NN, n = gq % NN;

    const float* xb = xyz + (size_t)b * 3 * NN;
    float x = xb[n], y = xb[NN + n], z = xb[2 * NN + n];
    float sq = fmaf(x, x, fmaf(y, y, z * z));
    g_xyzw[gq] = make_float4(x, y, z, sq);

    float acc[M0];
#pragma unroll
    for (int o = 0; o < M0; o++) acc[o] = 0.f;

    const float* pb = points + (size_t)b * DD * NN + n;
#pragma unroll 4
    for (int c = 0; c < DD; c++) {
        float p = pb[(size_t)c * NN];
        const float4* w4 = (const float4*)wfT[c];
#pragma unroll
        for (int o4 = 0; o4 < M0 / 4; o4++) {
            float4 w = w4[o4];
            acc[o4 * 4 + 0] = fmaf(w.x, p, acc[o4 * 4 + 0]);
            acc[o4 * 4 + 1] = fmaf(w.y, p, acc[o4 * 4 + 1]);
            acc[o4 * 4 + 2] = fmaf(w.z, p, acc[o4 * 4 + 2]);
            acc[o4 * 4 + 3] = fmaf(w.w, p, acc[o4 * 4 + 3]);
        }
    }
    float4* fo = (float4*)(g_feat + (size_t)gq * M0);
#pragma unroll
    for (int o4 = 0; o4 < M0 / 4; o4++)
        fo[o4] = make_float4(acc[o4 * 4 + 0], acc[o4 * 4 + 1],
                             acc[o4 * 4 + 2], acc[o4 * 4 + 3]);
}

// ---------------------------------------------------------------------------
// kNN consolidation: fold pending ring entries into exact top-16 (u64 lex
// keys, unsorted, worst tracked). Branchless replace + tournament.
// key = (monotone-flipped float bits of d) << 32 | idx  -> ascending key
// order == (d, idx) lexicographic == jax.lax.top_k order.
// ---------------------------------------------------------------------------
__device__ __forceinline__ void consolidate(unsigned long long (&slot)[KNB],
                                            unsigned long long& worstkey,
                                            float& worst_d, int& cnt,
                                            unsigned long long (*ring)[128],
                                            int tid) {
#pragma unroll 1
    for (int i = 0; i < cnt; i++) {
        unsigned long long e = ring[i][tid];
        unsigned db = (unsigned)(e >> 32);
        unsigned msk = ((unsigned)((int)db >> 31)) | 0x80000000u;
        unsigned long long key =
            ((unsigned long long)(db ^ msk) << 32) | (unsigned)e;
        if (key < worstkey) {
#pragma unroll
            for (int m = 0; m < KNB; m++)
                slot[m] = (slot[m] == worstkey) ? key : slot[m];
            unsigned long long w = slot[0];
#pragma unroll
            for (int m = 1; m < KNB; m++) w = (slot[m] > w) ? slot[m] : w;
            worstkey = w;
        }
    }
    cnt = 0;
    unsigned k32 = (unsigned)(worstkey >> 32);
    unsigned bits = (k32 & 0x80000000u) ? (k32 ^ 0x80000000u) : ~k32;
    worst_d = __uint_as_float(bits);
}

// ---------------------------------------------------------------------------
// Kernel 2: full-scan kNN, 1 thread = 1 query, branch-free hot path.
// grid (N/128, B), block 128.
// ---------------------------------------------------------------------------
__global__ void __launch_bounds__(128) knn_kernel(void) {
    __shared__ __align__(16) float4 tile[KTILE];
    __shared__ unsigned long long ring[RINGN][128];

    int tid = threadIdx.x;
    int b = blockIdx.y;
    int q = blockIdx.x * 128 + tid;

    float4 qf = g_xyzw[b * NN + q];
    float nqx = -2.f * qf.x, nqy = -2.f * qf.y, nqz = -2.f * qf.z;
    float qw = qf.w;

    unsigned long long slot[KNB];
#pragma unroll
    for (int m = 0; m < KNB; m++)
        slot[m] = 0xFF80000000000000ull | (unsigned)m;  // flip(+inf) | m
    unsigned long long worstkey = 0xFF80000000000000ull | (KNB - 1);
    float worst_d = __int_as_float(0x7F800000);  // +inf
    int cnt = 0;

    for (int t = 0; t < NN / KTILE; t++) {
        __syncthreads();
        const float4* src = &g_xyzw[b * NN + t * KTILE];
        for (int i = tid; i < KTILE; i += 128) tile[i] = src[i];
        __syncthreads();

#pragma unroll 1
        for (int j0 = 0; j0 < KTILE; j0 += 8) {
#pragma unroll
            for (int u = 0; u < 8; u++) {
                float4 c = tile[j0 + u];
                float d = fmaf(nqx, c.x,
                          fmaf(nqy, c.y, fmaf(nqz, c.z, qw + c.w)));
                if (d < worst_d) {
                    unsigned gj = (unsigned)(t * KTILE + j0 + u);
                    ring[cnt][tid] =
                        ((unsigned long long)__float_as_uint(d) << 32) | gj;
                    cnt++;
                }
            }
            if (__ballot_sync(0xffffffffu, cnt >= 16))
                consolidate(slot, worstkey, worst_d, cnt, ring, tid);
        }
    }
    if (__ballot_sync(0xffffffffu, cnt > 0))
        consolidate(slot, worstkey, worst_d, cnt, ring, tid);

    // bitonic sort 16 ascending (key = (d, idx) lex) -> jax top_k order
#pragma unroll
    for (int k = 2; k <= KNB; k <<= 1) {
#pragma unroll
        for (int jj = k >> 1; jj > 0; jj >>= 1) {
#pragma unroll
            for (int i = 0; i < KNB; i++) {
                int p = i ^ jj;
                if (p > i) {
                    bool up = ((i & k) == 0);
                    unsigned long long a = slot[i], bb2 = slot[p];
                    bool sw = (a > bb2) != up;
                    slot[i] = sw ? bb2 : a;
                    slot[p] = sw ? a : bb2;
                }
            }
        }
    }

    int4* op = (int4*)(g_idx + ((size_t)b * NN + q) * KNB);
#pragma unroll
    for (int m4 = 0; m4 < KNB / 4; m4++)
        op[m4] = make_int4((int)(unsigned)slot[m4 * 4 + 0],
                           (int)(unsigned)slot[m4 * 4 + 1],
                           (int)(unsigned)slot[m4 * 4 + 2],
                           (int)(unsigned)slot[m4 * 4 + 3]);
}

// ---------------------------------------------------------------------------
// Kernel 3: gather + 3-layer MLP (layers 1/2 on packed fma.rn.f32x2) + max
// over K. block 128 = 8 queries x 16 neighbor-threads. (measured 163us)
// ---------------------------------------------------------------------------
__global__ void __launch_bounds__(128) mlp_kernel(const float* __restrict__ W0,
                                                  const float* __restrict__ W1,
                                                  const float* __restrict__ W2,
                                                  float* __restrict__ out) {
    __shared__ __align__(16) float w0x[M0][4];
    __shared__ __align__(16) unsigned long long w1p[M0][M1 / 2];
    __shared__ __align__(16) unsigned long long w2p[M1][M2 / 2];
    __shared__ float stage[8][M2];

    int tid = threadIdx.x;
    for (int i = tid; i < M0 * 4; i += 128) {
        int o = i / 4, c = i % 4;
        w0x[o][c] = (c < 3) ? W0[o * 35 + c] : 0.f;
    }
    for (int i = tid; i < M0 * (M1 / 2); i += 128) {
        int c = i / (M1 / 2), p = i % (M1 / 2);
        w1p[c][p] = pk2(W1[(2 * p) * M0 + c], W1[(2 * p + 1) * M0 + c]);
    }
    for (int i = tid; i < M1 * (M2 / 2); i += 128) {
        int c = i / (M2 / 2), p = i % (M2 / 2);
        w2p[c][p] = pk2(W2[(2 * p) * M1 + c], W2[(2 * p + 1) * M1 + c]);
    }
    __syncthreads();

    int g = tid >> 4, k = tid & 15;
    int gq = blockIdx.x * 8 + g;
    int b = gq / NN;

    int j = g_idx[(size_t)gq * KNB + k];
    float4 qf = g_xyzw[gq];
    float4 cf = g_xyzw[b * NN + j];
    float rx = cf.x - qf.x, ry = cf.y - qf.y, rz = cf.z - qf.z;

    float h0[M0];
    const float4* fg = (const float4*)(g_feat + ((size_t)b * NN + j) * M0);
#pragma unroll
    for (int o4 = 0; o4 < M0 / 4; o4++) {
        float4 f = fg[o4];
        float fv[4] = {f.x, f.y, f.z, f.w};
#pragma unroll
        for (int u = 0; u < 4; u++) {
            float4 w = *(const float4*)w0x[o4 * 4 + u];
            h0[o4 * 4 + u] = lrelu(fmaf(w.x, rx, fmaf(w.y, ry, fmaf(w.z, rz, fv[u]))));
        }
    }

    unsigned long long acc1[M1 / 2];
#pragma unroll
    for (int p = 0; p < M1 / 2; p++) acc1[p] = 0ull;
#pragma unroll
    for (int c = 0; c < M0; c++) {
        unsigned long long hp = pk2(h0[c], h0[c]);
        const ulonglong2* wv = (const ulonglong2*)w1p[c];
#pragma unroll
        for (int p2 = 0; p2 < M1 / 4; p2++) {
            ulonglong2 w = wv[p2];
            acc1[2 * p2 + 0] = fma2(w.x, hp, acc1[2 * p2 + 0]);
            acc1[2 * p2 + 1] = fma2(w.y, hp, acc1[2 * p2 + 1]);
        }
    }
    unsigned long long h1p[M1];
#pragma unroll
    for (int p = 0; p < M1 / 2; p++) {
        float a, bv;
        upk2(acc1[p], a, bv);
        a = lrelu(a); bv = lrelu(bv);
        h1p[2 * p + 0] = pk2(a, a);
        h1p[2 * p + 1] = pk2(bv, bv);
    }

#pragma unroll 1
    for (int ch = 0; ch < M2 / 8; ch++) {
        unsigned long long a01 = 0ull, a23 = 0ull, a45 = 0ull, a67 = 0ull;
#pragma unroll
        for (int c = 0; c < M1; c++) {
            unsigned long long hp = h1p[c];
            const ulonglong2* wv = (const ulonglong2*)&w2p[c][ch * 4];
            ulonglong2 wa = wv[0], wb = wv[1];
            a01 = fma2(wa.x, hp, a01);
            a23 = fma2(wa.y, hp, a23);
            a45 = fma2(wb.x, hp, a45);
            a67 = fma2(wb.y, hp, a67);
        }
        float v[8];
        upk2(a01, v[0], v[1]);
        upk2(a23, v[2], v[3]);
        upk2(a45, v[4], v[5]);
        upk2(a67, v[6], v[7]);
#pragma unroll
        for (int u = 0; u < 8; u++) v[u] = lrelu(v[u]);
#pragma unroll
        for (int s = 8; s >= 1; s >>= 1) {
#pragma unroll
            for (int u = 0; u < 8; u++)
                v[u] = fmaxf(v[u], __shfl_xor_sync(0xffffffffu, v[u], s));
        }
        if (k == 0) {
#pragma unroll
            for (int u = 0; u < 8; u++) stage[g][ch * 8 + u] = v[u];
        }
    }
    __syncthreads();

    int gq0 = blockIdx.x * 8;
    int b0 = gq0 / NN, n0 = gq0 % NN;
    for (int i = tid; i < 8 * M2; i += 128) {
        int o = i >> 3, gi = i & 7;
        out[((size_t)b0 * M2 + o) * NN + (n0 + gi)] = stage[gi][o];
    }
}

extern "C" void kernel_launch(void* const* d_in, const int* in_sizes, int n_in,
                              void* d_out, int out_size) {
    const float* xyz    = (const float*)d_in[0];
    const float* points = (const float*)d_in[1];
    const float* W0     = (const float*)d_in[2];
    const float* W1     = (const float*)d_in[3];
    const float* W2     = (const float*)d_in[4];
    float* out = (float*)d_out;

    prep_kernel<<<BB * NN / 128, 128>>>(xyz, points, W0);

    dim3 g2(NN / 128, BB);
    knn_kernel<<<g2, 128>>>();

    mlp_kernel<<<BB * NN / 8, 128>>>(W0, W1, W2, out);
}

// round 5
// speedup vs baseline: 9.4041x; 1.1863x over previous
#include <cuda_runtime.h>

#define BB 4
#define NN 8192
#define DD 32
#define KNB 16
#define M0 32
#define M1 32
#define M2 64
#define LEAKY 0.1f
#define KTILE 512
#define RINGN 16
#define KBLK 256

__device__ float4 g_xyzw[BB * NN];
__device__ float  g_feat[BB * NN * M0];
__device__ int    g_idx[BB * NN * KNB];

__device__ __forceinline__ float lrelu(float x) { return x > 0.f ? x : LEAKY * x; }

__device__ __forceinline__ unsigned long long pk2(float lo, float hi) {
    unsigned long long r;
    asm("mov.b64 %0, {%1, %2};" : "=l"(r) : "f"(lo), "f"(hi));
    return r;
}
__device__ __forceinline__ void upk2(unsigned long long v, float& lo, float& hi) {
    asm("mov.b64 {%0, %1}, %2;" : "=f"(lo), "=f"(hi) : "l"(v));
}
__device__ __forceinline__ unsigned long long fma2(unsigned long long a,
                                                   unsigned long long b,
                                                   unsigned long long c) {
    unsigned long long d;
    asm("fma.rn.f32x2 %0, %1, %2, %3;" : "=l"(d) : "l"(a), "l"(b), "l"(c));
    return d;
}

// ---------------------------------------------------------------------------
// Kernel 1: pack xyz as float4(x,y,z,|p|^2); feat = W0[:,3:] @ points
// ---------------------------------------------------------------------------
__global__ void prep_kernel(const float* __restrict__ xyz,
                            const float* __restrict__ points,
                            const float* __restrict__ W0) {
    __shared__ __align__(16) float wfT[DD][M0];
    int tid = threadIdx.x;
    for (int i = tid; i < DD * M0; i += 128) {
        int c = i / M0, o = i % M0;
        wfT[c][o] = W0[o * 35 + 3 + c];
    }
    __syncthreads();

    int gq = blockIdx.x * 128 + tid;
    int b = gq / NN, n = gq % NN;

    const float* xb = xyz + (size_t)b * 3 * NN;
    float x = xb[n], y = xb[NN + n], z = xb[2 * NN + n];
    float sq = fmaf(x, x, fmaf(y, y, z * z));
    g_xyzw[gq] = make_float4(x, y, z, sq);

    float acc[M0];
#pragma unroll
    for (int o = 0; o < M0; o++) acc[o] = 0.f;

    const float* pb = points + (size_t)b * DD * NN + n;
#pragma unroll 4
    for (int c = 0; c < DD; c++) {
        float p = pb[(size_t)c * NN];
        const float4* w4 = (const float4*)wfT[c];
#pragma unroll
        for (int o4 = 0; o4 < M0 / 4; o4++) {
            float4 w = w4[o4];
            acc[o4 * 4 + 0] = fmaf(w.x, p, acc[o4 * 4 + 0]);
            acc[o4 * 4 + 1] = fmaf(w.y, p, acc[o4 * 4 + 1]);
            acc[o4 * 4 + 2] = fmaf(w.z, p, acc[o4 * 4 + 2]);
            acc[o4 * 4 + 3] = fmaf(w.w, p, acc[o4 * 4 + 3]);
        }
    }
    float4* fo = (float4*)(g_feat + (size_t)gq * M0);
#pragma unroll
    for (int o4 = 0; o4 < M0 / 4; o4++)
        fo[o4] = make_float4(acc[o4 * 4 + 0], acc[o4 * 4 + 1],
                             acc[o4 * 4 + 2], acc[o4 * 4 + 3]);
}

// ---------------------------------------------------------------------------
// kNN consolidation: fold pending ring entries into exact unsorted top-16
// (u64 lex keys = flipped-float(d)<<32 | idx). Branchless replace-worst.
// ---------------------------------------------------------------------------
__device__ __forceinline__ void consolidate(unsigned long long (&slot)[KNB],
                                            unsigned long long& worstkey,
                                            float& worst_d, int& cnt,
                                            unsigned long long (*ring)[KBLK],
                                            int tid) {
#pragma unroll 1
    for (int i = 0; i < cnt; i++) {
        unsigned long long e = ring[i][tid];
        unsigned db = (unsigned)(e >> 32);
        unsigned msk = ((unsigned)((int)db >> 31)) | 0x80000000u;
        unsigned long long key =
            ((unsigned long long)(db ^ msk) << 32) | (unsigned)e;
        if (key < worstkey) {
#pragma unroll
            for (int m = 0; m < KNB; m++)
                slot[m] = (slot[m] == worstkey) ? key : slot[m];
            unsigned long long w = slot[0];
#pragma unroll
            for (int m = 1; m < KNB; m++) w = (slot[m] > w) ? slot[m] : w;
            worstkey = w;
        }
    }
    cnt = 0;
    unsigned k32 = (unsigned)(worstkey >> 32);
    unsigned bits = (k32 & 0x80000000u) ? (k32 ^ 0x80000000u) : ~k32;
    worst_d = __uint_as_float(bits);
}

// ---------------------------------------------------------------------------
// Kernel 2: full-scan kNN, 4 threads per query (lane r scans j%4==r),
// branch-free hot path, exact in-warp butterfly merge at the end.
// block 256 = 64 queries x 4 subthreads. grid (N/64, B).
// ---------------------------------------------------------------------------
__global__ void __launch_bounds__(KBLK) knn_kernel(void) {
    __shared__ __align__(16) float4 tile[KTILE];
    __shared__ unsigned long long ring[RINGN][KBLK];

    int tid = threadIdx.x;
    int b = blockIdx.y;
    int q = blockIdx.x * (KBLK / 4) + (tid >> 2);
    int r = tid & 3;

    float4 qf = g_xyzw[b * NN + q];
    float nqx = -2.f * qf.x, nqy = -2.f * qf.y, nqz = -2.f * qf.z;
    float qw = qf.w;

    unsigned long long slot[KNB];
#pragma unroll
    for (int m = 0; m < KNB; m++)
        slot[m] = 0xFF80000000000000ull | (unsigned)m;  // flip(+inf) | m
    unsigned long long worstkey = 0xFF80000000000000ull | (KNB - 1);
    float worst_d = __int_as_float(0x7F800000);
    int cnt = 0;

    for (int t = 0; t < NN / KTILE; t++) {
        __syncthreads();
        const float4* src = &g_xyzw[b * NN + t * KTILE];
        for (int i = tid; i < KTILE; i += KBLK) tile[i] = src[i];
        __syncthreads();

#pragma unroll 1
        for (int j0 = 0; j0 < KTILE; j0 += 32) {
#pragma unroll
            for (int u = 0; u < 8; u++) {
                int jl = j0 + u * 4 + r;
                float4 c = tile[jl];
                float d = fmaf(nqx, c.x,
                          fmaf(nqy, c.y, fmaf(nqz, c.z, qw + c.w)));
                if (d < worst_d) {
                    unsigned gj = (unsigned)(t * KTILE + jl);
                    ring[cnt][tid] =
                        ((unsigned long long)__float_as_uint(d) << 32) | gj;
                    cnt++;
                }
            }
            // ring has 16 rows; threshold 9 guarantees cnt<=16 before drain
            if (__ballot_sync(0xffffffffu, cnt >= 9))
                consolidate(slot, worstkey, worst_d, cnt, ring, tid);
        }
    }
    if (__ballot_sync(0xffffffffu, cnt > 0))
        consolidate(slot, worstkey, worst_d, cnt, ring, tid);

    // bitonic sort own 16 ascending
#pragma unroll
    for (int k = 2; k <= KNB; k <<= 1) {
#pragma unroll
        for (int jj = k >> 1; jj > 0; jj >>= 1) {
#pragma unroll
            for (int i = 0; i < KNB; i++) {
                int p = i ^ jj;
                if (p > i) {
                    bool up = ((i & k) == 0);
                    unsigned long long a = slot[i], bb2 = slot[p];
                    bool sw = (a > bb2) != up;
                    slot[i] = sw ? bb2 : a;
                    slot[p] = sw ? a : bb2;
                }
            }
        }
    }

    // 2 butterfly merge rounds across the 4 subthreads (xor 1, then xor 2).
    // a, b sorted asc -> c[i] = min(a[i], b[15-i]) is the 16 smallest of the
    // union as a bitonic sequence; clean with 4 stages.
#pragma unroll
    for (int step = 1; step <= 2; step <<= 1) {
        unsigned long long other[KNB];
#pragma unroll
        for (int i = 0; i < KNB; i++)
            other[i] = __shfl_xor_sync(0xffffffffu, slot[i], step);
        unsigned long long c[KNB];
#pragma unroll
        for (int i = 0; i < KNB; i++) {
            unsigned long long bv = other[KNB - 1 - i];
            c[i] = (slot[i] < bv) ? slot[i] : bv;
        }
#pragma unroll
        for (int jj = KNB / 2; jj > 0; jj >>= 1) {
#pragma unroll
            for (int i = 0; i < KNB; i++) {
                if ((i & jj) == 0) {
                    int p = i | jj;
                    unsigned long long a = c[i], bb2 = c[p];
                    bool sw = (a > bb2);
                    c[i] = sw ? bb2 : a;
                    c[p] = sw ? a : bb2;
                }
            }
        }
#pragma unroll
        for (int i = 0; i < KNB; i++) slot[i] = c[i];
    }

    // lane r writes slot[4r..4r+3] -> coalesced 64B per query
    int4* op = (int4*)(g_idx + ((size_t)b * NN + q) * KNB + 4 * r);
    *op = make_int4((int)(unsigned)slot[4 * r + 0],
                    (int)(unsigned)slot[4 * r + 1],
                    (int)(unsigned)slot[4 * r + 2],
                    (int)(unsigned)slot[4 * r + 3]);
}

// ---------------------------------------------------------------------------
// Kernel 3: gather + 3-layer MLP (layers 1/2 on packed fma.rn.f32x2) + max
// over K. block 128 = 8 queries x 16 neighbor-threads. (measured 163us)
// ---------------------------------------------------------------------------
__global__ void __launch_bounds__(128) mlp_kernel(const float* __restrict__ W0,
                                                  const float* __restrict__ W1,
                                                  const float* __restrict__ W2,
                                                  float* __restrict__ out) {
    __shared__ __align__(16) float w0x[M0][4];
    __shared__ __align__(16) unsigned long long w1p[M0][M1 / 2];
    __shared__ __align__(16) unsigned long long w2p[M1][M2 / 2];
    __shared__ float stage[8][M2];

    int tid = threadIdx.x;
    for (int i = tid; i < M0 * 4; i += 128) {
        int o = i / 4, c = i % 4;
        w0x[o][c] = (c < 3) ? W0[o * 35 + c] : 0.f;
    }
    for (int i = tid; i < M0 * (M1 / 2); i += 128) {
        int c = i / (M1 / 2), p = i % (M1 / 2);
        w1p[c][p] = pk2(W1[(2 * p) * M0 + c], W1[(2 * p + 1) * M0 + c]);
    }
    for (int i = tid; i < M1 * (M2 / 2); i += 128) {
        int c = i / (M2 / 2), p = i % (M2 / 2);
        w2p[c][p] = pk2(W2[(2 * p) * M1 + c], W2[(2 * p + 1) * M1 + c]);
    }
    __syncthreads();

    int g = tid >> 4, k = tid & 15;
    int gq = blockIdx.x * 8 + g;
    int b = gq / NN;

    int j = g_idx[(size_t)gq * KNB + k];
    float4 qf = g_xyzw[gq];
    float4 cf = g_xyzw[b * NN + j];
    float rx = cf.x - qf.x, ry = cf.y - qf.y, rz = cf.z - qf.z;

    float h0[M0];
    const float4* fg = (const float4*)(g_feat + ((size_t)b * NN + j) * M0);
#pragma unroll
    for (int o4 = 0; o4 < M0 / 4; o4++) {
        float4 f = fg[o4];
        float fv[4] = {f.x, f.y, f.z, f.w};
#pragma unroll
        for (int u = 0; u < 4; u++) {
            float4 w = *(const float4*)w0x[o4 * 4 + u];
            h0[o4 * 4 + u] = lrelu(fmaf(w.x, rx, fmaf(w.y, ry, fmaf(w.z, rz, fv[u]))));
        }
    }

    unsigned long long acc1[M1 / 2];
#pragma unroll
    for (int p = 0; p < M1 / 2; p++) acc1[p] = 0ull;
#pragma unroll
    for (int c = 0; c < M0; c++) {
        unsigned long long hp = pk2(h0[c], h0[c]);
        const ulonglong2* wv = (const ulonglong2*)w1p[c];
#pragma unroll
        for (int p2 = 0; p2 < M1 / 4; p2++) {
            ulonglong2 w = wv[p2];
            acc1[2 * p2 + 0] = fma2(w.x, hp, acc1[2 * p2 + 0]);
            acc1[2 * p2 + 1] = fma2(w.y, hp, acc1[2 * p2 + 1]);
        }
    }
    unsigned long long h1p[M1];
#pragma unroll
    for (int p = 0; p < M1 / 2; p++) {
        float a, bv;
        upk2(acc1[p], a, bv);
        a = lrelu(a); bv = lrelu(bv);
        h1p[2 * p + 0] = pk2(a, a);
        h1p[2 * p + 1] = pk2(bv, bv);
    }

#pragma unroll 1
    for (int ch = 0; ch < M2 / 8; ch++) {
        unsigned long long a01 = 0ull, a23 = 0ull, a45 = 0ull, a67 = 0ull;
#pragma unroll
        for (int c = 0; c < M1; c++) {
            unsigned long long hp = h1p[c];
            const ulonglong2* wv = (const ulonglong2*)&w2p[c][ch * 4];
            ulonglong2 wa = wv[0], wb = wv[1];
            a01 = fma2(wa.x, hp, a01);
            a23 = fma2(wa.y, hp, a23);
            a45 = fma2(wb.x, hp, a45);
            a67 = fma2(wb.y, hp, a67);
        }
        float v[8];
        upk2(a01, v[0], v[1]);
        upk2(a23, v[2], v[3]);
        upk2(a45, v[4], v[5]);
        upk2(a67, v[6], v[7]);
#pragma unroll
        for (int u = 0; u < 8; u++) v[u] = lrelu(v[u]);
#pragma unroll
        for (int s = 8; s >= 1; s >>= 1) {
#pragma unroll
            for (int u = 0; u < 8; u++)
                v[u] = fmaxf(v[u], __shfl_xor_sync(0xffffffffu, v[u], s));
        }
        if (k == 0) {
#pragma unroll
            for (int u = 0; u < 8; u++) stage[g][ch * 8 + u] = v[u];
        }
    }
    __syncthreads();

    int gq0 = blockIdx.x * 8;
    int b0 = gq0 / NN, n0 = gq0 % NN;
    for (int i = tid; i < 8 * M2; i += 128) {
        int o = i >> 3, gi = i & 7;
        out[((size_t)b0 * M2 + o) * NN + (n0 + gi)] = stage[gi][o];
    }
}

extern "C" void kernel_launch(void* const* d_in, const int* in_sizes, int n_in,
                              void* d_out, int out_size) {
    const float* xyz    = (const float*)d_in[0];
    const float* points = (const float*)d_in[1];
    const float* W0     = (const float*)d_in[2];
    const float* W1     = (const float*)d_in[3];
    const float* W2     = (const float*)d_in[4];
    float* out = (float*)d_out;

    prep_kernel<<<BB * NN / 128, 128>>>(xyz, points, W0);

    dim3 g2(NN / (KBLK / 4), BB);
    knn_kernel<<<g2, KBLK>>>();

    mlp_kernel<<<BB * NN / 8, 128>>>(W0, W1, W2, out);
}

// round 6
// speedup vs baseline: 9.7642x; 1.0383x over previous
#include <cuda_runtime.h>

#define BB 4
#define NN 8192
#define DD 32
#define KNB 16
#define M0 32
#define M1 32
#define M2 64
#define LEAKY 0.1f
#define KTILE 512
#define RINGN 16
#define KBLK 256

__device__ float4 g_xyzw[BB * NN];
__device__ float  g_feat[BB * NN * M0];
__device__ int    g_idx[BB * NN * KNB];

__device__ __forceinline__ float lrelu(float x) { return x > 0.f ? x : LEAKY * x; }

__device__ __forceinline__ unsigned long long pk2(float lo, float hi) {
    unsigned long long r;
    asm("mov.b64 %0, {%1, %2};" : "=l"(r) : "f"(lo), "f"(hi));
    return r;
}
__device__ __forceinline__ void upk2(unsigned long long v, float& lo, float& hi) {
    asm("mov.b64 {%0, %1}, %2;" : "=f"(lo), "=f"(hi) : "l"(v));
}
__device__ __forceinline__ unsigned long long fma2(unsigned long long a,
                                                   unsigned long long b,
                                                   unsigned long long c) {
    unsigned long long d;
    asm("fma.rn.f32x2 %0, %1, %2, %3;" : "=l"(d) : "l"(a), "l"(b), "l"(c));
    return d;
}

// ---------------------------------------------------------------------------
// Kernel 1: pack xyz as float4(x,y,z,|p|^2); feat = W0[:,3:] @ points
// ---------------------------------------------------------------------------
__global__ void prep_kernel(const float* __restrict__ xyz,
                            const float* __restrict__ points,
                            const float* __restrict__ W0) {
    __shared__ __align__(16) float wfT[DD][M0];
    int tid = threadIdx.x;
    for (int i = tid; i < DD * M0; i += 128) {
        int c = i / M0, o = i % M0;
        wfT[c][o] = W0[o * 35 + 3 + c];
    }
    __syncthreads();

    int gq = blockIdx.x * 128 + tid;
    int b = gq / NN, n = gq % NN;

    const float* xb = xyz + (size_t)b * 3 * NN;
    float x = xb[n], y = xb[NN + n], z = xb[2 * NN + n];
    float sq = fmaf(x, x, fmaf(y, y, z * z));
    g_xyzw[gq] = make_float4(x, y, z, sq);

    float acc[M0];
#pragma unroll
    for (int o = 0; o < M0; o++) acc[o] = 0.f;

    const float* pb = points + (size_t)b * DD * NN + n;
#pragma unroll 4
    for (int c = 0; c < DD; c++) {
        float p = pb[(size_t)c * NN];
        const float4* w4 = (const float4*)wfT[c];
#pragma unroll
        for (int o4 = 0; o4 < M0 / 4; o4++) {
            float4 w = w4[o4];
            acc[o4 * 4 + 0] = fmaf(w.x, p, acc[o4 * 4 + 0]);
            acc[o4 * 4 + 1] = fmaf(w.y, p, acc[o4 * 4 + 1]);
            acc[o4 * 4 + 2] = fmaf(w.z, p, acc[o4 * 4 + 2]);
            acc[o4 * 4 + 3] = fmaf(w.w, p, acc[o4 * 4 + 3]);
        }
    }
    float4* fo = (float4*)(g_feat + (size_t)gq * M0);
#pragma unroll
    for (int o4 = 0; o4 < M0 / 4; o4++)
        fo[o4] = make_float4(acc[o4 * 4 + 0], acc[o4 * 4 + 1],
                             acc[o4 * 4 + 2], acc[o4 * 4 + 3]);
}

// ---------------------------------------------------------------------------
// kNN consolidation: fold pending ring entries into exact unsorted top-16
// (u64 lex keys = flipped-float(d)<<32 | idx). Branchless replace-worst.
// ---------------------------------------------------------------------------
__device__ __forceinline__ void consolidate(unsigned long long (&slot)[KNB],
                                            unsigned long long& worstkey,
                                            float& worst_d, int& cnt,
                                            unsigned long long (*ring)[KBLK],
                                            int tid) {
#pragma unroll 1
    for (int i = 0; i < cnt; i++) {
        unsigned long long e = ring[i][tid];
        unsigned db = (unsigned)(e >> 32);
        unsigned msk = ((unsigned)((int)db >> 31)) | 0x80000000u;
        unsigned long long key =
            ((unsigned long long)(db ^ msk) << 32) | (unsigned)e;
        if (key < worstkey) {
#pragma unroll
            for (int m = 0; m < KNB; m++)
                slot[m] = (slot[m] == worstkey) ? key : slot[m];
            unsigned long long w = slot[0];
#pragma unroll
            for (int m = 1; m < KNB; m++) w = (slot[m] > w) ? slot[m] : w;
            worstkey = w;
        }
    }
    cnt = 0;
    unsigned k32 = (unsigned)(worstkey >> 32);
    unsigned bits = (k32 & 0x80000000u) ? (k32 ^ 0x80000000u) : ~k32;
    worst_d = __uint_as_float(bits);
}

// ---------------------------------------------------------------------------
// Kernel 2: full-scan kNN, 4 threads per query (lane r scans j%4==r).
// Hot path: mask-based acceptance (no cnt serial chain), shared quad
// threshold (exact), in-warp butterfly merge at the end.
// block 256 = 64 queries x 4 subthreads. grid (N/64, B).
// ---------------------------------------------------------------------------
__global__ void __launch_bounds__(KBLK) knn_kernel(void) {
    __shared__ __align__(16) float4 tile[KTILE];
    __shared__ unsigned long long ring[RINGN][KBLK];

    int tid = threadIdx.x;
    int b = blockIdx.y;
    int q = blockIdx.x * (KBLK / 4) + (tid >> 2);
    int r = tid & 3;

    float4 qf = g_xyzw[b * NN + q];
    float nqx = -2.f * qf.x, nqy = -2.f * qf.y, nqz = -2.f * qf.z;
    float qw = qf.w;

    unsigned long long slot[KNB];
#pragma unroll
    for (int m = 0; m < KNB; m++)
        slot[m] = 0xFF80000000000000ull | (unsigned)m;  // flip(+inf) | m
    unsigned long long worstkey = 0xFF80000000000000ull | (KNB - 1);
    float worst_d = __int_as_float(0x7F800000);
    float thresh  = __int_as_float(0x7F800000);
    int cnt = 0;

    for (int t = 0; t < NN / KTILE; t++) {
        __syncthreads();
        const float4* src = &g_xyzw[b * NN + t * KTILE];
        for (int i = tid; i < KTILE; i += KBLK) tile[i] = src[i];
        __syncthreads();

#pragma unroll 1
        for (int j0 = 0; j0 < KTILE; j0 += 32) {
            float dv[8];
            unsigned m = 0;
#pragma unroll
            for (int u = 0; u < 8; u++) {
                float4 c = tile[j0 + u * 4 + r];
                dv[u] = fmaf(nqx, c.x,
                        fmaf(nqy, c.y, fmaf(nqz, c.z, qw + c.w)));
                m |= (dv[u] <= thresh) ? (1u << u) : 0u;
            }
            // independent predicated stores; positions via popc prefix
#pragma unroll
            for (int u = 0; u < 8; u++) {
                if (m & (1u << u)) {
                    unsigned gj = (unsigned)(t * KTILE + j0 + u * 4 + r);
                    ring[cnt + __popc(m & ((1u << u) - 1))][tid] =
                        ((unsigned long long)__float_as_uint(dv[u]) << 32) | gj;
                }
            }
            cnt += __popc(m);
            if (__ballot_sync(0xffffffffu, cnt >= 9)) {
                consolidate(slot, worstkey, worst_d, cnt, ring, tid);
                // exact shared threshold: min of the 4 lanes' 16th-best.
                // rejection d > thresh is safe: the min-lane holds 16
                // strictly better entries that survive to the final merge.
                float tt = fminf(worst_d,
                                 __shfl_xor_sync(0xffffffffu, worst_d, 1));
                tt = fminf(tt, __shfl_xor_sync(0xffffffffu, tt, 2));
                thresh = tt;
            }
        }
    }
    if (__ballot_sync(0xffffffffu, cnt > 0))
        consolidate(slot, worstkey, worst_d, cnt, ring, tid);

    // bitonic sort own 16 ascending (lex key order == jax top_k order)
#pragma unroll
    for (int k = 2; k <= KNB; k <<= 1) {
#pragma unroll
        for (int jj = k >> 1; jj > 0; jj >>= 1) {
#pragma unroll
            for (int i = 0; i < KNB; i++) {
                int p = i ^ jj;
                if (p > i) {
                    bool up = ((i & k) == 0);
                    unsigned long long a = slot[i], bb2 = slot[p];
                    bool sw = (a > bb2) != up;
                    slot[i] = sw ? bb2 : a;
                    slot[p] = sw ? a : bb2;
                }
            }
        }
    }

    // 2 butterfly merge rounds across the 4 subthreads (xor 1, then xor 2)
#pragma unroll
    for (int step = 1; step <= 2; step <<= 1) {
        unsigned long long other[KNB];
#pragma unroll
        for (int i = 0; i < KNB; i++)
            other[i] = __shfl_xor_sync(0xffffffffu, slot[i], step);
        unsigned long long c[KNB];
#pragma unroll
        for (int i = 0; i < KNB; i++) {
            unsigned long long bv = other[KNB - 1 - i];
            c[i] = (slot[i] < bv) ? slot[i] : bv;
        }
#pragma unroll
        for (int jj = KNB / 2; jj > 0; jj >>= 1) {
#pragma unroll
            for (int i = 0; i < KNB; i++) {
                if ((i & jj) == 0) {
                    int p = i | jj;
                    unsigned long long a = c[i], bb2 = c[p];
                    bool sw = (a > bb2);
                    c[i] = sw ? bb2 : a;
                    c[p] = sw ? a : bb2;
                }
            }
        }
#pragma unroll
        for (int i = 0; i < KNB; i++) slot[i] = c[i];
    }

    int4* op = (int4*)(g_idx + ((size_t)b * NN + q) * KNB + 4 * r);
    *op = make_int4((int)(unsigned)slot[4 * r + 0],
                    (int)(unsigned)slot[4 * r + 1],
                    (int)(unsigned)slot[4 * r + 2],
                    (int)(unsigned)slot[4 * r + 3]);
}

// ---------------------------------------------------------------------------
// Kernel 3: gather + 3-layer MLP (layers 1/2 on packed fma.rn.f32x2) + max
// over K. block 128 = 8 queries x 16 neighbor-threads. h1 kept as scalar
// floats (splat on use) to cut ~32 regs -> 4 blocks/SM.
// ---------------------------------------------------------------------------
__global__ void __launch_bounds__(128) mlp_kernel(const float* __restrict__ W0,
                                                  const float* __restrict__ W1,
                                                  const float* __restrict__ W2,
                                                  float* __restrict__ out) {
    __shared__ __align__(16) float w0x[M0][4];
    __shared__ __align__(16) unsigned long long w1p[M0][M1 / 2];
    __shared__ __align__(16) unsigned long long w2p[M1][M2 / 2];
    __shared__ float stage[8][M2];

    int tid = threadIdx.x;
    for (int i = tid; i < M0 * 4; i += 128) {
        int o = i / 4, c = i % 4;
        w0x[o][c] = (c < 3) ? W0[o * 35 + c] : 0.f;
    }
    for (int i = tid; i < M0 * (M1 / 2); i += 128) {
        int c = i / (M1 / 2), p = i % (M1 / 2);
        w1p[c][p] = pk2(W1[(2 * p) * M0 + c], W1[(2 * p + 1) * M0 + c]);
    }
    for (int i = tid; i < M1 * (M2 / 2); i += 128) {
        int c = i / (M2 / 2), p = i % (M2 / 2);
        w2p[c][p] = pk2(W2[(2 * p) * M1 + c], W2[(2 * p + 1) * M1 + c]);
    }
    __syncthreads();

    int g = tid >> 4, k = tid & 15;
    int gq = blockIdx.x * 8 + g;
    int b = gq / NN;

    int j = g_idx[(size_t)gq * KNB + k];
    float4 qf = g_xyzw[gq];
    float4 cf = g_xyzw[b * NN + j];
    float rx = cf.x - qf.x, ry = cf.y - qf.y, rz = cf.z - qf.z;

    float h0[M0];
    const float4* fg = (const float4*)(g_feat + ((size_t)b * NN + j) * M0);
#pragma unroll
    for (int o4 = 0; o4 < M0 / 4; o4++) {
        float4 f = fg[o4];
        float fv[4] = {f.x, f.y, f.z, f.w};
#pragma unroll
        for (int u = 0; u < 4; u++) {
            float4 w = *(const float4*)w0x[o4 * 4 + u];
            h0[o4 * 4 + u] = lrelu(fmaf(w.x, rx, fmaf(w.y, ry, fmaf(w.z, rz, fv[u]))));
        }
    }

    unsigned long long acc1[M1 / 2];
#pragma unroll
    for (int p = 0; p < M1 / 2; p++) acc1[p] = 0ull;
#pragma unroll
    for (int c = 0; c < M0; c++) {
        unsigned long long hp = pk2(h0[c], h0[c]);
        const ulonglong2* wv = (const ulonglong2*)w1p[c];
#pragma unroll
        for (int p2 = 0; p2 < M1 / 4; p2++) {
            ulonglong2 w = wv[p2];
            acc1[2 * p2 + 0] = fma2(w.x, hp, acc1[2 * p2 + 0]);
            acc1[2 * p2 + 1] = fma2(w.y, hp, acc1[2 * p2 + 1]);
        }
    }
    // h1 as scalar floats (regs) — splat per use in layer 2
    float h1[M1];
#pragma unroll
    for (int p = 0; p < M1 / 2; p++) {
        float a, bv;
        upk2(acc1[p], a, bv);
        h1[2 * p + 0] = lrelu(a);
        h1[2 * p + 1] = lrelu(bv);
    }

#pragma unroll 1
    for (int ch = 0; ch < M2 / 8; ch++) {
        unsigned long long a01 = 0ull, a23 = 0ull, a45 = 0ull, a67 = 0ull;
#pragma unroll
        for (int c = 0; c < M1; c++) {
            unsigned long long hp = pk2(h1[c], h1[c]);
            const ulonglong2* wv = (const ulonglong2*)&w2p[c][ch * 4];
            ulonglong2 wa = wv[0], wb = wv[1];
            a01 = fma2(wa.x, hp, a01);
            a23 = fma2(wa.y, hp, a23);
            a45 = fma2(wb.x, hp, a45);
            a67 = fma2(wb.y, hp, a67);
        }
        float v[8];
        upk2(a01, v[0], v[1]);
        upk2(a23, v[2], v[3]);
        upk2(a45, v[4], v[5]);
        upk2(a67, v[6], v[7]);
#pragma unroll
        for (int u = 0; u < 8; u++) v[u] = lrelu(v[u]);
#pragma unroll
        for (int s = 8; s >= 1; s >>= 1) {
#pragma unroll
            for (int u = 0; u < 8; u++)
                v[u] = fmaxf(v[u], __shfl_xor_sync(0xffffffffu, v[u], s));
        }
        if (k == 0) {
#pragma unroll
            for (int u = 0; u < 8; u++) stage[g][ch * 8 + u] = v[u];
        }
    }
    __syncthreads();

    int gq0 = blockIdx.x * 8;
    int b0 = gq0 / NN, n0 = gq0 % NN;
    for (int i = tid; i < 8 * M2; i += 128) {
        int o = i >> 3, gi = i & 7;
        out[((size_t)b0 * M2 + o) * NN + (n0 + gi)] = stage[gi][o];
    }
}

extern "C" void kernel_launch(void* const* d_in, const int* in_sizes, int n_in,
                              void* d_out, int out_size) {
    const float* xyz    = (const float*)d_in[0];
    const float* points = (const float*)d_in[1];
    const float* W0     = (const float*)d_in[2];
    const float* W1     = (const float*)d_in[3];
    const float* W2     = (const float*)d_in[4];
    float* out = (float*)d_out;

    prep_kernel<<<BB * NN / 128, 128>>>(xyz, points, W0);

    dim3 g2(NN / (KBLK / 4), BB);
    knn_kernel<<<g2, KBLK>>>();

    mlp_kernel<<<BB * NN / 8, 128>>>(W0, W1, W2, out);
}